// round 2
// baseline (speedup 1.0000x reference)
#include <cuda_runtime.h>
#include <cstddef>

#define H_  160
#define W_  160
#define B_  4
#define HW  (H_ * W_)

// ---------------- scratch (device globals: no allocation allowed) ----------
__device__ float g_buf1[(size_t)B_ * 256 * HW];   // 104.9 MB
__device__ float g_buf2[(size_t)B_ * 128 * HW];   //  52.4 MB
__device__ float g_mean[256];
__device__ float g_invstd[256];

// ---------------- main conv: 3x3, stride 1, pad 1, fp32 --------------------
// Block tile: 32 output channels x (8 rows x 32 cols) pixels for one batch.
// Thread: 4 oc x (2x4) pixels = 32 accumulators.
#define TH  8
#define TW  32
#define OCT 32
#define KC  8

__global__ __launch_bounds__(256, 2)
void conv3x3_tiled(const float* __restrict__ X, const float* __restrict__ Wt,
                   float* __restrict__ Y, int Cin, int Cout)
{
    const int tile = blockIdx.x;               // 0..99
    const int tw0  = (tile % (W_ / TW)) * TW;
    const int th0  = (tile / (W_ / TW)) * TH;
    const int oc0  = blockIdx.y * OCT;
    const int b    = blockIdx.z;

    __shared__ float sX[KC][TH + 2][TW + 4];   // row stride 36 floats
    __shared__ float sW[KC][9][OCT];           // [ci][tap][oc] for LDS.128

    const int t     = threadIdx.x;
    const int ocsub = t >> 5;                  // 0..7 (== warp id -> broadcast weights)
    const int p     = t & 31;
    const int r0    = (p >> 3) * 2;            // 0,2,4,6
    const int c0    = (p & 7) * 4;             // 0..28

    float acc[4][2][4];
    #pragma unroll
    for (int a = 0; a < 4; a++)
        #pragma unroll
        for (int r = 0; r < 2; r++)
            #pragma unroll
            for (int c = 0; c < 4; c++) acc[a][r][c] = 0.f;

    const float* Xb = X + (size_t)b * Cin * HW;

    for (int ci0 = 0; ci0 < Cin; ci0 += KC) {
        __syncthreads();
        // ---- load input tile KC x 10 x 34 (zero-padded halo) ----
        for (int e = t; e < KC * 10 * 34; e += 256) {
            int ci  = e / 340;
            int rem = e % 340;
            int r   = rem / 34;
            int c   = rem % 34;
            int gh  = th0 + r - 1;
            int gw  = tw0 + c - 1;
            float v = 0.f;
            if (gh >= 0 && gh < H_ && gw >= 0 && gw < W_)
                v = Xb[(size_t)(ci0 + ci) * HW + gh * W_ + gw];
            sX[ci][r][c] = v;
        }
        // ---- load weight tile (coalesced over tap,ci; scatter into smem) ----
        for (int e = t; e < KC * OCT * 9; e += 256) {
            int tap = e % 9;
            int ci  = (e / 9) % KC;
            int oc  = e / (9 * KC);
            sW[ci][tap][oc] = Wt[((size_t)(oc0 + oc) * Cin + ci0 + ci) * 9 + tap];
        }
        __syncthreads();

        #pragma unroll 1
        for (int ci = 0; ci < KC; ci++) {
            float w[4][9];
            #pragma unroll
            for (int tp = 0; tp < 9; tp++) {
                // 4 consecutive oc -> LDS.128, same address across the warp (broadcast)
                const float4 wv = *(const float4*)&sW[ci][tp][ocsub * 4];
                w[0][tp] = wv.x; w[1][tp] = wv.y; w[2][tp] = wv.z; w[3][tp] = wv.w;
            }
            float xv[4][6];
            #pragma unroll
            for (int rr = 0; rr < 4; rr++) {
                const float4 a = *(const float4*)&sX[ci][r0 + rr][c0];
                xv[rr][0] = a.x; xv[rr][1] = a.y; xv[rr][2] = a.z; xv[rr][3] = a.w;
                xv[rr][4] = sX[ci][r0 + rr][c0 + 4];
                xv[rr][5] = sX[ci][r0 + rr][c0 + 5];
            }
            #pragma unroll
            for (int mr = 0; mr < 4; mr++)
                #pragma unroll
                for (int orow = 0; orow < 2; orow++)
                    #pragma unroll
                    for (int ocol = 0; ocol < 4; ocol++) {
                        float s = acc[mr][orow][ocol];
                        #pragma unroll
                        for (int kh = 0; kh < 3; kh++)
                            #pragma unroll
                            for (int kw = 0; kw < 3; kw++)
                                s += w[mr][kh * 3 + kw] * xv[orow + kh][ocol + kw];
                        acc[mr][orow][ocol] = s;
                    }
        }
    }

    // ---- write out (float4 stores) ----
    #pragma unroll
    for (int mr = 0; mr < 4; mr++) {
        const int oc = oc0 + ocsub * 4 + mr;
        float* Yp = Y + ((size_t)b * Cout + oc) * HW;
        #pragma unroll
        for (int orow = 0; orow < 2; orow++) {
            const int h = th0 + r0 + orow;
            float4 v = make_float4(acc[mr][orow][0], acc[mr][orow][1],
                                   acc[mr][orow][2], acc[mr][orow][3]);
            *(float4*)&Yp[h * W_ + tw0 + c0] = v;
        }
    }
}

// ---------------- per-channel batch stats (train-mode BN) ------------------
__global__ void bn_stats(const float* __restrict__ X, int C)
{
    const int c = blockIdx.x;
    float s = 0.f, s2 = 0.f;
    for (int b = 0; b < B_; b++) {
        const float* q = X + ((size_t)b * C + c) * HW;
        for (int i = threadIdx.x; i < HW; i += 256) {
            float v = q[i];
            s += v; s2 += v * v;
        }
    }
    __shared__ float rs[256], rs2[256];
    rs[threadIdx.x] = s; rs2[threadIdx.x] = s2;
    __syncthreads();
    for (int o = 128; o > 0; o >>= 1) {
        if (threadIdx.x < o) {
            rs[threadIdx.x]  += rs[threadIdx.x + o];
            rs2[threadIdx.x] += rs2[threadIdx.x + o];
        }
        __syncthreads();
    }
    if (threadIdx.x == 0) {
        const float cnt = (float)(B_ * HW);
        float m   = rs[0] / cnt;
        float var = rs2[0] / cnt - m * m;
        g_mean[c]   = m;
        g_invstd[c] = rsqrtf(var + 1e-5f);
    }
}

// ---------------- fused BN apply + ReLU (in place) -------------------------
__global__ void bn_relu(float* __restrict__ X, const float* __restrict__ gamma,
                        const float* __restrict__ beta, int C)
{
    const size_t i = (size_t)blockIdx.x * 256 + threadIdx.x;
    const int c = (int)((i / HW) % C);
    float v = X[i];
    v = (v - g_mean[c]) * g_invstd[c] * gamma[c] + beta[c];
    X[i] = v > 0.f ? v : 0.f;
}

// ---------------- head conv: 3x3 + bias, small Cout -------------------------
#define HTH 16
#define HTW 32

template <int CO>
__global__ __launch_bounds__(256)
void head_conv(const float* __restrict__ X, const float* __restrict__ Wt,
               const float* __restrict__ bias, float* __restrict__ Y, int Cin)
{
    const int tile = blockIdx.x;                 // 0..49
    const int tw0  = (tile % (W_ / HTW)) * HTW;
    const int th0  = (tile / (W_ / HTW)) * HTH;
    const int b    = blockIdx.z;
    const int t    = threadIdx.x;
    const int col  = t & 31;
    const int rp   = (t >> 5) * 2;               // row pair base 0..14

    __shared__ float sX[8][HTH + 2][HTW + 4];
    __shared__ float sW[8][9][CO];

    float acc[2][CO];
    #pragma unroll
    for (int r = 0; r < 2; r++)
        #pragma unroll
        for (int o = 0; o < CO; o++) acc[r][o] = 0.f;

    const float* Xb = X + (size_t)b * Cin * HW;

    for (int ci0 = 0; ci0 < Cin; ci0 += 8) {
        __syncthreads();
        for (int e = t; e < 8 * (HTH + 2) * 34; e += 256) {
            int ci  = e / ((HTH + 2) * 34);
            int rem = e % ((HTH + 2) * 34);
            int r   = rem / 34;
            int c   = rem % 34;
            int gh  = th0 + r - 1;
            int gw  = tw0 + c - 1;
            float v = 0.f;
            if (gh >= 0 && gh < H_ && gw >= 0 && gw < W_)
                v = Xb[(size_t)(ci0 + ci) * HW + gh * W_ + gw];
            sX[ci][r][c] = v;
        }
        for (int e = t; e < 8 * 9 * CO; e += 256) {
            int ci  = e / (9 * CO);
            int rem = e % (9 * CO);
            int tap = rem / CO;
            int oc  = rem % CO;
            sW[ci][tap][oc] = Wt[((size_t)oc * Cin + ci0 + ci) * 9 + tap];
        }
        __syncthreads();

        #pragma unroll 1
        for (int ci = 0; ci < 8; ci++) {
            float xv[4][3];
            #pragma unroll
            for (int rr = 0; rr < 4; rr++)
                #pragma unroll
                for (int cc = 0; cc < 3; cc++)
                    xv[rr][cc] = sX[ci][rp + rr][col + cc];
            #pragma unroll
            for (int oc = 0; oc < CO; oc++) {
                float w[9];
                #pragma unroll
                for (int tp = 0; tp < 9; tp++) w[tp] = sW[ci][tp][oc];
                #pragma unroll
                for (int orow = 0; orow < 2; orow++) {
                    float s = acc[orow][oc];
                    #pragma unroll
                    for (int kh = 0; kh < 3; kh++)
                        #pragma unroll
                        for (int kw = 0; kw < 3; kw++)
                            s += w[kh * 3 + kw] * xv[orow + kh][kw];
                    acc[orow][oc] = s;
                }
            }
        }
    }

    #pragma unroll
    for (int oc = 0; oc < CO; oc++) {
        const float bz = bias[oc];
        #pragma unroll
        for (int orow = 0; orow < 2; orow++) {
            const int h = th0 + rp + orow;
            Y[((size_t)b * CO + oc) * HW + h * W_ + tw0 + col] = acc[orow][oc] + bz;
        }
    }
}

// ---------------- launcher ---------------------------------------------------
static void run_branch(const float* fpn,
                       const float* w1, const float* g1, const float* b1,
                       const float* w2, const float* g2, const float* b2,
                       float* buf1, float* buf2)
{
    dim3 cg1(100, 256 / OCT, B_);
    dim3 cg2(100, 128 / OCT, B_);
    conv3x3_tiled<<<cg1, 256>>>(fpn, w1, buf1, 256, 256);
    bn_stats<<<256, 256>>>(buf1, 256);
    bn_relu<<<(unsigned)((size_t)B_ * 256 * HW / 256), 256>>>(buf1, g1, b1, 256);
    conv3x3_tiled<<<cg2, 256>>>(buf1, w2, buf2, 256, 128);
    bn_stats<<<128, 256>>>(buf2, 128);
    bn_relu<<<(unsigned)((size_t)B_ * 128 * HW / 256), 256>>>(buf2, g2, b2, 128);
}

extern "C" void kernel_launch(void* const* d_in, const int* in_sizes, int n_in,
                              void* d_out, int out_size)
{
    const float* fpn        = (const float*)d_in[0];
    const float* w_sc1      = (const float*)d_in[1];
    const float* g_sc1      = (const float*)d_in[2];
    const float* b_sc1      = (const float*)d_in[3];
    const float* w_sc2      = (const float*)d_in[4];
    const float* g_sc2      = (const float*)d_in[5];
    const float* b_sc2      = (const float*)d_in[6];
    const float* w_shrink   = (const float*)d_in[7];
    const float* bias_shrink= (const float*)d_in[8];
    const float* w_cent     = (const float*)d_in[9];
    const float* bias_cent  = (const float*)d_in[10];
    const float* w_p1       = (const float*)d_in[11];
    const float* g_p1       = (const float*)d_in[12];
    const float* b_p1       = (const float*)d_in[13];
    const float* w_p2       = (const float*)d_in[14];
    const float* g_p2       = (const float*)d_in[15];
    const float* b_p2       = (const float*)d_in[16];
    const float* w_p3       = (const float*)d_in[17];
    const float* bias_p3    = (const float*)d_in[18];
    const float* w_s1       = (const float*)d_in[19];
    const float* g_s1       = (const float*)d_in[20];
    const float* b_s1       = (const float*)d_in[21];
    const float* w_s2       = (const float*)d_in[22];
    const float* g_s2       = (const float*)d_in[23];
    const float* b_s2       = (const float*)d_in[24];
    const float* w_s3       = (const float*)d_in[25];
    const float* bias_s3    = (const float*)d_in[26];

    float* out = (float*)d_out;

    float *buf1 = nullptr, *buf2 = nullptr;
    cudaGetSymbolAddress((void**)&buf1, g_buf1);
    cudaGetSymbolAddress((void**)&buf2, g_buf2);

    dim3 hgrid(50, 1, B_);
    const size_t seg = (size_t)B_ * HW;   // 102400

    // sc branch -> shrink, centroid
    run_branch(fpn, w_sc1, g_sc1, b_sc1, w_sc2, g_sc2, b_sc2, buf1, buf2);
    head_conv<1><<<hgrid, 256>>>(buf2, w_shrink, bias_shrink, out + 0,       128);
    head_conv<1><<<hgrid, 256>>>(buf2, w_cent,   bias_cent,   out + seg,     128);

    // param branch -> param (2 ch)
    run_branch(fpn, w_p1, g_p1, b_p1, w_p2, g_p2, b_p2, buf1, buf2);
    head_conv<2><<<hgrid, 256>>>(buf2, w_p3, bias_p3, out + 2 * seg, 128);

    // shift branch -> shift (8 ch)
    run_branch(fpn, w_s1, g_s1, b_s1, w_s2, g_s2, b_s2, buf1, buf2);
    head_conv<8><<<hgrid, 256>>>(buf2, w_s3, bias_s3, out + 4 * seg, 128);
}

// round 4
// speedup vs baseline: 3.0754x; 3.0754x over previous
#include <cuda_runtime.h>
#include <cstdint>
#include <cstddef>

#define H_   160
#define W_   160
#define B_   4
#define HW   (H_ * W_)
#define PIX  (B_ * HW)          // 102400
#define K2   2304               // 9 * 256
#define NCHK 72                 // K chunks of 32

// ---------------- scratch (device globals; no allocation allowed) ----------
__device__ float g_buf1[(size_t)B_ * 256 * HW];   // 104.9 MB
__device__ float g_buf2[(size_t)B_ * 128 * HW];   //  52.4 MB
__device__ float g_mean[256];
__device__ float g_invstd[256];
__device__ float g_wt[256 * K2];                  // k-major tf32 weights

__device__ __forceinline__ float to_tf32(float x) {
    float r; asm("cvt.rna.tf32.f32 %0, %1;" : "=f"(r) : "f"(x)); return r;
}

// mma.sync m16n8k8 tf32 (baseline PTX, valid on plain sm_103 target)
__device__ __forceinline__ void mma8(float* d, const uint32_t* a, uint32_t b0, uint32_t b1) {
    asm volatile(
        "mma.sync.aligned.m16n8k8.row.col.f32.tf32.tf32.f32 "
        "{%0,%1,%2,%3}, {%4,%5,%6,%7}, {%8,%9}, {%0,%1,%2,%3};"
        : "+f"(d[0]), "+f"(d[1]), "+f"(d[2]), "+f"(d[3])
        : "r"(a[0]), "r"(a[1]), "r"(a[2]), "r"(a[3]), "r"(b0), "r"(b1));
}

// smem geometry (floats)
#define SA_STR   136                 // 128 + 8 pad
#define SB_STR   264                 // 256 + 8 pad
#define A_FLTS   (32 * SA_STR)       // 4352
#define B_FLTS   (32 * SB_STR)       // 8448
#define STG_FLTS (A_FLTS + B_FLTS)   // 12800
#define SMEM_DYN (2 * STG_FLTS * 4)  // 102400 B

// ---------------- weight transform: [oc][ci][tap] -> tf32 [tap][ci][oc] ----
__global__ void wt_transform(const float* __restrict__ w, float* __restrict__ dst,
                             int Cout, int total)
{
    int i = blockIdx.x * 256 + threadIdx.x;
    if (i >= total) return;
    int oc = i % Cout;
    int t2 = i / Cout;
    int ci = t2 % 256;
    int tap = t2 / 256;
    dst[i] = to_tf32(w[((size_t)oc * 256 + ci) * 9 + tap]);
}

// ---------------- mma.sync tf32 implicit-GEMM 3x3 conv ----------------------
// grid: (PIX/256, Cout/128)  block: 512 threads (16 warps, warp = 32oc x 64px)
__global__ __launch_bounds__(512, 1)
void conv3x3_mma(const float* __restrict__ X, const float* __restrict__ wt,
                 float* __restrict__ Y, int Cout)
{
    extern __shared__ float sm[];

    const int tid  = threadIdx.x;
    const int wid  = tid >> 5;
    const int lane = tid & 31;
    const int r    = lane >> 2;      // fragment row group
    const int q    = lane & 3;       // fragment k/col group

    const int p0   = blockIdx.x * 256;      // 256 contiguous pixels (one image)
    const int oc0  = blockIdx.y * 128;
    const int bimg = p0 / HW;
    const int hw0  = p0 - bimg * HW;
    const float* Xb = X + (size_t)bimg * 256 * HW;

    // warp tile position
    const int ocb = (wid & 3) * 32;          // oc sub-block
    const int pxb = (wid >> 2) * 64;         // px sub-block

    // B staging geometry: this thread loads ch quad cw*4.., px groups gw*4..+3
    const int cw = wid & 7;
    const int gw = wid >> 3;
    int pg[4], hh[4], ww[4];
    #pragma unroll
    for (int g = 0; g < 4; g++) {
        int p = hw0 + (gw * 4 + g) * 32 + lane;
        pg[g] = p; hh[g] = p / W_; ww[g] = p % W_;
    }

    float acc[2][8][4];
    #pragma unroll
    for (int mt = 0; mt < 2; mt++)
        #pragma unroll
        for (int nt = 0; nt < 8; nt++)
            #pragma unroll
            for (int i = 0; i < 4; i++) acc[mt][nt][i] = 0.f;

    float4 ra[2];
    float  rb[4][4];

    auto stage = [&](int c) {
        const int tap = c >> 3;
        const int ci0 = (c & 7) << 5;
        const int dh  = tap / 3 - 1;
        const int dw  = tap % 3 - 1;
        // A: rows k = p*16+wid, cols lane*4 (coalesced LDG.128)
        const float* wrA = wt + ((size_t)(tap * 256 + ci0)) * Cout + oc0;
        #pragma unroll
        for (int p = 0; p < 2; p++)
            ra[p] = *(const float4*)(wrA + (size_t)(p * 16 + wid) * Cout + lane * 4);
        // B: im2col gather, 4 ch x 4 px-groups
        const float* Xc = Xb + (size_t)(ci0 + cw * 4) * HW + dh * W_ + dw;
        #pragma unroll
        for (int g = 0; g < 4; g++) {
            bool v = (unsigned)(hh[g] + dh) < (unsigned)H_ &&
                     (unsigned)(ww[g] + dw) < (unsigned)W_;
            const float* sp = Xc + pg[g];
            #pragma unroll
            for (int j = 0; j < 4; j++)
                rb[g][j] = v ? to_tf32(sp[(size_t)j * HW]) : 0.f;
        }
    };

    auto sts = [&](int s) {
        float* sA = sm + s * STG_FLTS;
        float* sB = sA + A_FLTS;
        #pragma unroll
        for (int p = 0; p < 2; p++)
            *(float4*)&sA[(p * 16 + wid) * SA_STR + lane * 4] = ra[p];
        #pragma unroll
        for (int g = 0; g < 4; g++)
            #pragma unroll
            for (int j = 0; j < 4; j++)
                sB[(cw * 4 + j) * SB_STR + (gw * 4 + g) * 32 + lane] = rb[g][j];
    };

    auto compute = [&](int s) {
        const float* sA = sm + s * STG_FLTS;
        const float* sB = sA + A_FLTS;
        #pragma unroll
        for (int ks = 0; ks < 4; ks++) {
            const float* aP = sA + (ks * 8 + q) * SA_STR + ocb + r;
            const float* bP = sB + (ks * 8 + q) * SB_STR + pxb + r;
            uint32_t a[2][4];
            #pragma unroll
            for (int mt = 0; mt < 2; mt++) {
                a[mt][0] = __float_as_uint(aP[mt * 16]);
                a[mt][1] = __float_as_uint(aP[mt * 16 + 8]);
                a[mt][2] = __float_as_uint(aP[4 * SA_STR + mt * 16]);
                a[mt][3] = __float_as_uint(aP[4 * SA_STR + mt * 16 + 8]);
            }
            #pragma unroll
            for (int nt = 0; nt < 8; nt++) {
                uint32_t b0 = __float_as_uint(bP[nt * 8]);
                uint32_t b1 = __float_as_uint(bP[4 * SB_STR + nt * 8]);
                mma8(acc[0][nt], a[0], b0, b1);
                mma8(acc[1][nt], a[1], b0, b1);
            }
        }
    };

    // 2-stage pipeline
    stage(0); sts(0);
    __syncthreads();
    for (int c = 0; c < NCHK; c++) {
        if (c + 1 < NCHK) stage(c + 1);
        compute(c & 1);
        if (c + 1 < NCHK) {
            sts((c + 1) & 1);
            __syncthreads();
        }
    }

    // epilogue: direct STG.64 per fragment pair
    #pragma unroll
    for (int mt = 0; mt < 2; mt++) {
        const int oc = oc0 + ocb + mt * 16 + r;
        float* Yr = Y + ((size_t)bimg * Cout + oc) * HW + hw0 + pxb + q * 2;
        #pragma unroll
        for (int nt = 0; nt < 8; nt++) {
            float2 lo = make_float2(acc[mt][nt][0], acc[mt][nt][1]);
            float2 hi = make_float2(acc[mt][nt][2], acc[mt][nt][3]);
            *(float2*)(Yr + nt * 8)               = lo;
            *(float2*)(Yr + nt * 8 + 8 * (size_t)HW) = hi;
        }
    }
}

// ---------------- per-channel batch stats (train-mode BN) ------------------
__global__ void bn_stats(const float* __restrict__ X, int C)
{
    const int c = blockIdx.x;
    float s = 0.f, s2 = 0.f;
    for (int b = 0; b < B_; b++) {
        const float* qp = X + ((size_t)b * C + c) * HW;
        for (int i = threadIdx.x; i < HW; i += 256) {
            float v = qp[i];
            s += v; s2 += v * v;
        }
    }
    __shared__ float rs[256], rs2[256];
    rs[threadIdx.x] = s; rs2[threadIdx.x] = s2;
    __syncthreads();
    for (int o = 128; o > 0; o >>= 1) {
        if (threadIdx.x < o) {
            rs[threadIdx.x]  += rs[threadIdx.x + o];
            rs2[threadIdx.x] += rs2[threadIdx.x + o];
        }
        __syncthreads();
    }
    if (threadIdx.x == 0) {
        const float cnt = (float)(B_ * HW);
        float m   = rs[0] / cnt;
        float var = rs2[0] / cnt - m * m;
        g_mean[c]   = m;
        g_invstd[c] = rsqrtf(var + 1e-5f);
    }
}

// ---------------- fused BN apply + ReLU (in place, float4, no div) ---------
__global__ void bn_relu(float* __restrict__ X, const float* __restrict__ gamma,
                        const float* __restrict__ beta, int C)
{
    const int c = blockIdx.y;
    const int b = blockIdx.z;
    const float m  = g_mean[c];
    const float is = g_invstd[c];
    const float ga = gamma[c];
    const float be = beta[c];
    float4* p = (float4*)(X + ((size_t)b * C + c) * HW) + blockIdx.x * 256 + threadIdx.x;
    float4 v = *p;
    v.x = fmaxf((v.x - m) * is * ga + be, 0.f);
    v.y = fmaxf((v.y - m) * is * ga + be, 0.f);
    v.z = fmaxf((v.z - m) * is * ga + be, 0.f);
    v.w = fmaxf((v.w - m) * is * ga + be, 0.f);
    *p = v;
}

// ---------------- head conv: 3x3 + bias, small Cout -------------------------
#define HTH 16
#define HTW 32

template <int CO>
__global__ __launch_bounds__(256)
void head_conv(const float* __restrict__ X, const float* __restrict__ Wt,
               const float* __restrict__ bias, float* __restrict__ Y, int Cin)
{
    const int tile = blockIdx.x;
    const int tw0  = (tile % (W_ / HTW)) * HTW;
    const int th0  = (tile / (W_ / HTW)) * HTH;
    const int b    = blockIdx.z;
    const int t    = threadIdx.x;
    const int col  = t & 31;
    const int rp   = (t >> 5) * 2;

    __shared__ float sX[8][HTH + 2][HTW + 4];
    __shared__ float sW[8][9][CO];

    float acc[2][CO];
    #pragma unroll
    for (int r = 0; r < 2; r++)
        #pragma unroll
        for (int o = 0; o < CO; o++) acc[r][o] = 0.f;

    const float* Xb = X + (size_t)b * Cin * HW;

    for (int ci0 = 0; ci0 < Cin; ci0 += 8) {
        __syncthreads();
        for (int e = t; e < 8 * (HTH + 2) * 34; e += 256) {
            int ci  = e / ((HTH + 2) * 34);
            int rem = e % ((HTH + 2) * 34);
            int r   = rem / 34;
            int c   = rem % 34;
            int gh  = th0 + r - 1;
            int gw  = tw0 + c - 1;
            float v = 0.f;
            if (gh >= 0 && gh < H_ && gw >= 0 && gw < W_)
                v = Xb[(size_t)(ci0 + ci) * HW + gh * W_ + gw];
            sX[ci][r][c] = v;
        }
        for (int e = t; e < 8 * 9 * CO; e += 256) {
            int ci  = e / (9 * CO);
            int rem = e % (9 * CO);
            int tap = rem / CO;
            int oc  = rem % CO;
            sW[ci][tap][oc] = Wt[((size_t)oc * Cin + ci0 + ci) * 9 + tap];
        }
        __syncthreads();

        #pragma unroll 1
        for (int ci = 0; ci < 8; ci++) {
            float xv[4][3];
            #pragma unroll
            for (int rr = 0; rr < 4; rr++)
                #pragma unroll
                for (int cc = 0; cc < 3; cc++)
                    xv[rr][cc] = sX[ci][rp + rr][col + cc];
            #pragma unroll
            for (int oc = 0; oc < CO; oc++) {
                float w[9];
                #pragma unroll
                for (int tp = 0; tp < 9; tp++) w[tp] = sW[ci][tp][oc];
                #pragma unroll
                for (int orow = 0; orow < 2; orow++) {
                    float s = acc[orow][oc];
                    #pragma unroll
                    for (int kh = 0; kh < 3; kh++)
                        #pragma unroll
                        for (int kw = 0; kw < 3; kw++)
                            s += w[kh * 3 + kw] * xv[orow + kh][kw];
                    acc[orow][oc] = s;
                }
            }
        }
    }

    #pragma unroll
    for (int oc = 0; oc < CO; oc++) {
        const float bz = bias[oc];
        #pragma unroll
        for (int orow = 0; orow < 2; orow++) {
            const int h = th0 + rp + orow;
            Y[((size_t)b * CO + oc) * HW + h * W_ + tw0 + col] = acc[orow][oc] + bz;
        }
    }
}

// ---------------- launcher ---------------------------------------------------
static void run_branch(const float* fpn,
                       const float* w1, const float* g1, const float* b1,
                       const float* w2, const float* g2, const float* b2,
                       float* buf1, float* buf2, float* wtbuf)
{
    dim3 bnr1(HW / 4 / 256, 256, B_);
    dim3 bnr2(HW / 4 / 256, 128, B_);
    wt_transform<<<(256 * K2 + 255) / 256, 256>>>(w1, wtbuf, 256, 256 * K2);
    conv3x3_mma<<<dim3(PIX / 256, 2), 512, SMEM_DYN>>>(fpn, wtbuf, buf1, 256);
    bn_stats<<<256, 256>>>(buf1, 256);
    bn_relu<<<bnr1, 256>>>(buf1, g1, b1, 256);
    wt_transform<<<(128 * K2 + 255) / 256, 256>>>(w2, wtbuf, 128, 128 * K2);
    conv3x3_mma<<<dim3(PIX / 256, 1), 512, SMEM_DYN>>>(buf1, wtbuf, buf2, 128);
    bn_stats<<<128, 256>>>(buf2, 128);
    bn_relu<<<bnr2, 256>>>(buf2, g2, b2, 128);
}

extern "C" void kernel_launch(void* const* d_in, const int* in_sizes, int n_in,
                              void* d_out, int out_size)
{
    const float* fpn        = (const float*)d_in[0];
    const float* w_sc1      = (const float*)d_in[1];
    const float* g_sc1      = (const float*)d_in[2];
    const float* b_sc1      = (const float*)d_in[3];
    const float* w_sc2      = (const float*)d_in[4];
    const float* g_sc2      = (const float*)d_in[5];
    const float* b_sc2      = (const float*)d_in[6];
    const float* w_shrink   = (const float*)d_in[7];
    const float* bias_shrink= (const float*)d_in[8];
    const float* w_cent     = (const float*)d_in[9];
    const float* bias_cent  = (const float*)d_in[10];
    const float* w_p1       = (const float*)d_in[11];
    const float* g_p1       = (const float*)d_in[12];
    const float* b_p1       = (const float*)d_in[13];
    const float* w_p2       = (const float*)d_in[14];
    const float* g_p2       = (const float*)d_in[15];
    const float* b_p2       = (const float*)d_in[16];
    const float* w_p3       = (const float*)d_in[17];
    const float* bias_p3    = (const float*)d_in[18];
    const float* w_s1       = (const float*)d_in[19];
    const float* g_s1       = (const float*)d_in[20];
    const float* b_s1       = (const float*)d_in[21];
    const float* w_s2       = (const float*)d_in[22];
    const float* g_s2       = (const float*)d_in[23];
    const float* b_s2       = (const float*)d_in[24];
    const float* w_s3       = (const float*)d_in[25];
    const float* bias_s3    = (const float*)d_in[26];

    float* out = (float*)d_out;

    float *buf1 = nullptr, *buf2 = nullptr, *wtbuf = nullptr;
    cudaGetSymbolAddress((void**)&buf1, g_buf1);
    cudaGetSymbolAddress((void**)&buf2, g_buf2);
    cudaGetSymbolAddress((void**)&wtbuf, g_wt);

    cudaFuncSetAttribute(conv3x3_mma, cudaFuncAttributeMaxDynamicSharedMemorySize, SMEM_DYN);

    dim3 hgrid(50, 1, B_);
    const size_t seg = (size_t)B_ * HW;

    run_branch(fpn, w_sc1, g_sc1, b_sc1, w_sc2, g_sc2, b_sc2, buf1, buf2, wtbuf);
    head_conv<1><<<hgrid, 256>>>(buf2, w_shrink, bias_shrink, out + 0,   128);
    head_conv<1><<<hgrid, 256>>>(buf2, w_cent,   bias_cent,   out + seg, 128);

    run_branch(fpn, w_p1, g_p1, b_p1, w_p2, g_p2, b_p2, buf1, buf2, wtbuf);
    head_conv<2><<<hgrid, 256>>>(buf2, w_p3, bias_p3, out + 2 * seg, 128);

    run_branch(fpn, w_s1, g_s1, b_s1, w_s2, g_s2, b_s2, buf1, buf2, wtbuf);
    head_conv<8><<<hgrid, 256>>>(buf2, w_s3, bias_s3, out + 4 * seg, 128);
}

// round 5
// speedup vs baseline: 3.8646x; 1.2566x over previous
#include <cuda_runtime.h>
#include <cstdint>
#include <cstddef>

#define H_   160
#define W_   160
#define B_   4
#define HW   (H_ * W_)
#define PIX  (B_ * HW)          // 102400
#define K2   2304               // 9 * 256
#define NCHK 72                 // K chunks of 32

// ---------------- scratch (device globals; no allocation allowed) ----------
__device__ float g_buf1[3][(size_t)B_ * 256 * HW];
__device__ float g_buf2[3][(size_t)B_ * 128 * HW];
__device__ float g_wt1[3][2 * 72 * 4096];         // packed conv1 weights
__device__ float g_wt2[3][1 * 72 * 4096];         // packed conv2 weights
__device__ float g_sc1[3][256], g_bi1[3][256];
__device__ float g_sc2[3][128], g_bi2[3][128];

__device__ __forceinline__ float to_tf32(float x) {
    float r; asm("cvt.rna.tf32.f32 %0, %1;" : "=f"(r) : "f"(x)); return r;
}

// mma.sync m16n8k8 tf32 (baseline PTX, valid on plain sm_103 target)
__device__ __forceinline__ void mma8(float* d, const uint32_t* a, uint32_t b0, uint32_t b1) {
    asm volatile(
        "mma.sync.aligned.m16n8k8.row.col.f32.tf32.tf32.f32 "
        "{%0,%1,%2,%3}, {%4,%5,%6,%7}, {%8,%9}, {%0,%1,%2,%3};"
        : "+f"(d[0]), "+f"(d[1]), "+f"(d[2]), "+f"(d[3])
        : "r"(a[0]), "r"(a[1]), "r"(a[2]), "r"(a[3]), "r"(b0), "r"(b1));
}

// smem: per stage A packed 4096 floats + B [32k][136] = 4352 floats
#define SB_STR   136
#define STG_FLTS (4096 + 32 * SB_STR)    // 8448
#define SMEM_DYN (2 * STG_FLTS * 4)      // 67584 B

// ---------------- weight pack: [oc][ci][tap] -> fragment-ordered tf32 ------
// out idx = ((((ocblk*72 + chunk)*4 + ks)*4 + og)*2 + mt)*128 + lane*4 + j
__global__ void wt_pack(const float* __restrict__ w, float* __restrict__ dst, int Cout)
{
    int i = blockIdx.x * 256 + threadIdx.x;
    if (i >= Cout * K2) return;
    int j     = i & 3;
    int lane  = (i >> 2) & 31;
    int mt    = (i >> 7) & 1;
    int og    = (i >> 8) & 3;
    int ks    = (i >> 10) & 3;
    int chunk = (i >> 12) % 72;
    int ocblk = i / (72 * 4096);
    int q = lane & 3, r = lane >> 2;
    int tap = chunk >> 3;
    int ci  = (chunk & 7) * 32 + ks * 8 + q + (j >> 1) * 4;
    int oc  = ocblk * 128 + og * 32 + r + mt * 16 + (j & 1) * 8;
    dst[i] = to_tf32(w[((size_t)oc * 256 + ci) * 9 + tap]);
}

// ---------------- mma.sync tf32 implicit-GEMM 3x3 conv ----------------------
// grid: (PIX/128, Cout/128)  block: 256 threads (8 warps, warp = 32oc x 64px)
template <bool HAS_BN>
__global__ __launch_bounds__(256, 2)
void conv3x3_mma(const float* __restrict__ X, const float* __restrict__ wtp,
                 float* __restrict__ Y, int Cout,
                 const float* __restrict__ bnsc, const float* __restrict__ bnbi)
{
    extern __shared__ float sm[];

    const int tid  = threadIdx.x;
    const int wid  = tid >> 5;
    const int lane = tid & 31;
    const int r    = lane >> 2;
    const int q    = lane & 3;

    const int p0   = blockIdx.x * 128;
    const int oc0  = blockIdx.y * 128;
    const int bimg = p0 / HW;
    const int hw0  = p0 - bimg * HW;
    const float* Xb  = X + (size_t)bimg * 256 * HW;
    const float* wcb = wtp + (size_t)blockIdx.y * (72 * 4096);

    const int ocb = (wid & 3) * 32;
    const int pxb = (wid >> 2) * 64;
    const int cw  = wid;                       // channel quad owner for B staging

    int pg[4], hh[4], ww[4];
    #pragma unroll
    for (int g = 0; g < 4; g++) {
        int p = hw0 + g * 32 + lane;
        pg[g] = p; hh[g] = p / W_; ww[g] = p % W_;
    }

    float acc[2][8][4];
    #pragma unroll
    for (int mt = 0; mt < 2; mt++)
        #pragma unroll
        for (int nt = 0; nt < 8; nt++)
            #pragma unroll
            for (int i = 0; i < 4; i++) acc[mt][nt][i] = 0.f;

    float4 ra[4];
    float  rb[4][4];

    auto stage = [&](int c) {
        const int tap = c >> 3;
        const int ci0 = (c & 7) << 5;
        const int dh  = tap / 3 - 1;
        const int dw  = tap % 3 - 1;
        // A: linear copy of fragment-packed chunk
        const float4* pA = (const float4*)(wcb + (size_t)c * 4096);
        #pragma unroll
        for (int i = 0; i < 4; i++) ra[i] = pA[tid + i * 256];
        // B: im2col gather (+ fused BN/ReLU of producer when HAS_BN)
        float sc[4], bi[4];
        if (HAS_BN) {
            #pragma unroll
            for (int j = 0; j < 4; j++) {
                sc[j] = bnsc[ci0 + cw * 4 + j];
                bi[j] = bnbi[ci0 + cw * 4 + j];
            }
        }
        const float* Xc = Xb + (size_t)(ci0 + cw * 4) * HW + dh * W_ + dw;
        #pragma unroll
        for (int g = 0; g < 4; g++) {
            bool v = (unsigned)(hh[g] + dh) < (unsigned)H_ &&
                     (unsigned)(ww[g] + dw) < (unsigned)W_;
            const float* sp = Xc + pg[g];
            #pragma unroll
            for (int j = 0; j < 4; j++) {
                float x = v ? sp[(size_t)j * HW] : 0.f;
                if (HAS_BN) x = v ? fmaxf(fmaf(x, sc[j], bi[j]), 0.f) : 0.f;
                rb[g][j] = to_tf32(x);
            }
        }
    };

    auto sts = [&](int s) {
        float* sA = sm + s * STG_FLTS;
        float4* dA = (float4*)sA;
        #pragma unroll
        for (int i = 0; i < 4; i++) dA[tid + i * 256] = ra[i];
        float* sB = sA + 4096;
        #pragma unroll
        for (int g = 0; g < 4; g++)
            #pragma unroll
            for (int j = 0; j < 4; j++)
                sB[(cw * 4 + j) * SB_STR + g * 32 + lane] = rb[g][j];
    };

    auto compute = [&](int s) {
        const float* sA = sm + s * STG_FLTS;
        const float* sB = sA + 4096;
        #pragma unroll
        for (int ks = 0; ks < 4; ks++) {
            const float* ap = sA + ks * 1024 + (wid & 3) * 256 + lane * 4;
            float4 qa0 = *(const float4*)ap;
            float4 qa1 = *(const float4*)(ap + 128);
            uint32_t a0[4] = { __float_as_uint(qa0.x), __float_as_uint(qa0.y),
                               __float_as_uint(qa0.z), __float_as_uint(qa0.w) };
            uint32_t a1[4] = { __float_as_uint(qa1.x), __float_as_uint(qa1.y),
                               __float_as_uint(qa1.z), __float_as_uint(qa1.w) };
            const float* bP = sB + (ks * 8 + q) * SB_STR + pxb + r;
            #pragma unroll
            for (int nt = 0; nt < 8; nt++) {
                uint32_t b0 = __float_as_uint(bP[nt * 8]);
                uint32_t b1 = __float_as_uint(bP[nt * 8 + 4 * SB_STR]);
                mma8(acc[0][nt], a0, b0, b1);
                mma8(acc[1][nt], a1, b0, b1);
            }
        }
    };

    stage(0); sts(0);
    __syncthreads();
    for (int c = 0; c < NCHK; c++) {
        if (c + 1 < NCHK) stage(c + 1);
        compute(c & 1);
        if (c + 1 < NCHK) {
            sts((c + 1) & 1);
            __syncthreads();
        }
    }

    #pragma unroll
    for (int mt = 0; mt < 2; mt++) {
        const int oc = oc0 + ocb + mt * 16 + r;
        float* Yr = Y + ((size_t)bimg * Cout + oc) * HW + hw0 + pxb + q * 2;
        #pragma unroll
        for (int nt = 0; nt < 8; nt++) {
            *(float2*)(Yr + nt * 8)                  = make_float2(acc[mt][nt][0], acc[mt][nt][1]);
            *(float2*)(Yr + nt * 8 + 8 * (size_t)HW) = make_float2(acc[mt][nt][2], acc[mt][nt][3]);
        }
    }
}

// ---------------- per-channel batch stats -> fused scale/bias ---------------
__global__ void bn_stats(const float* __restrict__ X, int C,
                         const float* __restrict__ gamma, const float* __restrict__ beta,
                         float* __restrict__ osc, float* __restrict__ obi)
{
    const int c = blockIdx.x;
    float s = 0.f, s2 = 0.f;
    for (int b = 0; b < B_; b++) {
        const float* qp = X + ((size_t)b * C + c) * HW;
        for (int i = threadIdx.x; i < HW; i += 256) {
            float v = qp[i];
            s += v; s2 += v * v;
        }
    }
    __shared__ float rs[256], rs2[256];
    rs[threadIdx.x] = s; rs2[threadIdx.x] = s2;
    __syncthreads();
    for (int o = 128; o > 0; o >>= 1) {
        if (threadIdx.x < o) {
            rs[threadIdx.x]  += rs[threadIdx.x + o];
            rs2[threadIdx.x] += rs2[threadIdx.x + o];
        }
        __syncthreads();
    }
    if (threadIdx.x == 0) {
        const float cnt = (float)(B_ * HW);
        float m   = rs[0] / cnt;
        float var = rs2[0] / cnt - m * m;
        float is  = rsqrtf(var + 1e-5f);
        float scl = gamma[c] * is;
        osc[c] = scl;
        obi[c] = beta[c] - m * scl;
    }
}

// ---------------- head conv: 3x3 + bias, BN+ReLU fused on input -------------
#define HTH 16
#define HTW 32

template <int CO>
__global__ __launch_bounds__(256)
void head_conv(const float* __restrict__ X, const float* __restrict__ Wt,
               const float* __restrict__ bias, float* __restrict__ Y, int Cin,
               const float* __restrict__ bnsc, const float* __restrict__ bnbi)
{
    const int tile = blockIdx.x;
    const int tw0  = (tile % (W_ / HTW)) * HTW;
    const int th0  = (tile / (W_ / HTW)) * HTH;
    const int b    = blockIdx.z;
    const int t    = threadIdx.x;
    const int col  = t & 31;
    const int rp   = (t >> 5) * 2;

    __shared__ float sX[8][HTH + 2][HTW + 4];
    __shared__ float sW[8][9][CO];

    float acc[2][CO];
    #pragma unroll
    for (int r = 0; r < 2; r++)
        #pragma unroll
        for (int o = 0; o < CO; o++) acc[r][o] = 0.f;

    const float* Xb = X + (size_t)b * Cin * HW;

    for (int ci0 = 0; ci0 < Cin; ci0 += 8) {
        __syncthreads();
        for (int e = t; e < 8 * (HTH + 2) * 34; e += 256) {
            int ci  = e / ((HTH + 2) * 34);
            int rem = e % ((HTH + 2) * 34);
            int r   = rem / 34;
            int c   = rem % 34;
            int gh  = th0 + r - 1;
            int gw  = tw0 + c - 1;
            float v = 0.f;
            if (gh >= 0 && gh < H_ && gw >= 0 && gw < W_) {
                float x = Xb[(size_t)(ci0 + ci) * HW + gh * W_ + gw];
                v = fmaxf(fmaf(x, bnsc[ci0 + ci], bnbi[ci0 + ci]), 0.f);
            }
            sX[ci][r][c] = v;
        }
        for (int e = t; e < 8 * 9 * CO; e += 256) {
            int ci  = e / (9 * CO);
            int rem = e % (9 * CO);
            int tap = rem / CO;
            int oc  = rem % CO;
            sW[ci][tap][oc] = Wt[((size_t)oc * Cin + ci0 + ci) * 9 + tap];
        }
        __syncthreads();

        #pragma unroll 1
        for (int ci = 0; ci < 8; ci++) {
            float xv[4][3];
            #pragma unroll
            for (int rr = 0; rr < 4; rr++)
                #pragma unroll
                for (int cc = 0; cc < 3; cc++)
                    xv[rr][cc] = sX[ci][rp + rr][col + cc];
            #pragma unroll
            for (int oc = 0; oc < CO; oc++) {
                float w[9];
                #pragma unroll
                for (int tp = 0; tp < 9; tp++) w[tp] = sW[ci][tp][oc];
                #pragma unroll
                for (int orow = 0; orow < 2; orow++) {
                    float s = acc[orow][oc];
                    #pragma unroll
                    for (int kh = 0; kh < 3; kh++)
                        #pragma unroll
                        for (int kw = 0; kw < 3; kw++)
                            s += w[kh * 3 + kw] * xv[orow + kh][kw];
                    acc[orow][oc] = s;
                }
            }
        }
    }

    #pragma unroll
    for (int oc = 0; oc < CO; oc++) {
        const float bz = bias[oc];
        #pragma unroll
        for (int orow = 0; orow < 2; orow++) {
            const int h = th0 + rp + orow;
            Y[((size_t)b * CO + oc) * HW + h * W_ + tw0 + col] = acc[orow][oc] + bz;
        }
    }
}

// ---------------- launcher ---------------------------------------------------
struct BranchPtrs {
    const float *w1, *g1, *b1, *w2, *g2, *b2;
};

static void run_branch(int bi, cudaStream_t st, const float* fpn, const BranchPtrs& P,
                       float* buf1, float* buf2, float* wt1, float* wt2,
                       float* sc1, float* bi1, float* sc2, float* bi2)
{
    wt_pack<<<(256 * K2 + 255) / 256, 256, 0, st>>>(P.w1, wt1, 256);
    wt_pack<<<(128 * K2 + 255) / 256, 256, 0, st>>>(P.w2, wt2, 128);
    conv3x3_mma<false><<<dim3(PIX / 128, 2), 256, SMEM_DYN, st>>>(
        fpn, wt1, buf1, 256, nullptr, nullptr);
    bn_stats<<<256, 256, 0, st>>>(buf1, 256, P.g1, P.b1, sc1, bi1);
    conv3x3_mma<true><<<dim3(PIX / 128, 1), 256, SMEM_DYN, st>>>(
        buf1, wt2, buf2, 128, sc1, bi1);
    bn_stats<<<128, 256, 0, st>>>(buf2, 128, P.g2, P.b2, sc2, bi2);
}

extern "C" void kernel_launch(void* const* d_in, const int* in_sizes, int n_in,
                              void* d_out, int out_size)
{
    const float* fpn        = (const float*)d_in[0];
    BranchPtrs sc = { (const float*)d_in[1],  (const float*)d_in[2],  (const float*)d_in[3],
                      (const float*)d_in[4],  (const float*)d_in[5],  (const float*)d_in[6] };
    const float* w_shrink   = (const float*)d_in[7];
    const float* bias_shrink= (const float*)d_in[8];
    const float* w_cent     = (const float*)d_in[9];
    const float* bias_cent  = (const float*)d_in[10];
    BranchPtrs pp = { (const float*)d_in[11], (const float*)d_in[12], (const float*)d_in[13],
                      (const float*)d_in[14], (const float*)d_in[15], (const float*)d_in[16] };
    const float* w_p3       = (const float*)d_in[17];
    const float* bias_p3    = (const float*)d_in[18];
    BranchPtrs sh = { (const float*)d_in[19], (const float*)d_in[20], (const float*)d_in[21],
                      (const float*)d_in[22], (const float*)d_in[23], (const float*)d_in[24] };
    const float* w_s3       = (const float*)d_in[25];
    const float* bias_s3    = (const float*)d_in[26];

    float* out = (float*)d_out;

    static cudaStream_t s_st[3];
    static cudaEvent_t  s_fork, s_join[3];
    static int s_init = 0;
    if (!s_init) {
        for (int i = 0; i < 3; i++) {
            cudaStreamCreateWithFlags(&s_st[i], cudaStreamNonBlocking);
            cudaEventCreateWithFlags(&s_join[i], cudaEventDisableTiming);
        }
        cudaEventCreateWithFlags(&s_fork, cudaEventDisableTiming);
        s_init = 1;
    }

    float *buf1[3], *buf2[3], *wt1[3], *wt2[3];
    float *sc1[3], *bi1[3], *sc2[3], *bi2[3];
    {
        float *p;
        cudaGetSymbolAddress((void**)&p, g_buf1);
        for (int i = 0; i < 3; i++) buf1[i] = p + (size_t)i * B_ * 256 * HW;
        cudaGetSymbolAddress((void**)&p, g_buf2);
        for (int i = 0; i < 3; i++) buf2[i] = p + (size_t)i * B_ * 128 * HW;
        cudaGetSymbolAddress((void**)&p, g_wt1);
        for (int i = 0; i < 3; i++) wt1[i] = p + (size_t)i * 2 * 72 * 4096;
        cudaGetSymbolAddress((void**)&p, g_wt2);
        for (int i = 0; i < 3; i++) wt2[i] = p + (size_t)i * 72 * 4096;
        cudaGetSymbolAddress((void**)&p, g_sc1);
        for (int i = 0; i < 3; i++) sc1[i] = p + i * 256;
        cudaGetSymbolAddress((void**)&p, g_bi1);
        for (int i = 0; i < 3; i++) bi1[i] = p + i * 256;
        cudaGetSymbolAddress((void**)&p, g_sc2);
        for (int i = 0; i < 3; i++) sc2[i] = p + i * 128;
        cudaGetSymbolAddress((void**)&p, g_bi2);
        for (int i = 0; i < 3; i++) bi2[i] = p + i * 128;
    }

    cudaFuncSetAttribute(conv3x3_mma<false>, cudaFuncAttributeMaxDynamicSharedMemorySize, SMEM_DYN);
    cudaFuncSetAttribute(conv3x3_mma<true>,  cudaFuncAttributeMaxDynamicSharedMemorySize, SMEM_DYN);

    dim3 hgrid(50, 1, B_);
    const size_t seg = (size_t)B_ * HW;

    // fork
    cudaEventRecord(s_fork, 0);
    for (int i = 0; i < 3; i++) cudaStreamWaitEvent(s_st[i], s_fork, 0);

    // branch 0: sc -> shrink + centroid
    run_branch(0, s_st[0], fpn, sc, buf1[0], buf2[0], wt1[0], wt2[0],
               sc1[0], bi1[0], sc2[0], bi2[0]);
    head_conv<1><<<hgrid, 256, 0, s_st[0]>>>(buf2[0], w_shrink, bias_shrink,
                                             out + 0,   128, sc2[0], bi2[0]);
    head_conv<1><<<hgrid, 256, 0, s_st[0]>>>(buf2[0], w_cent, bias_cent,
                                             out + seg, 128, sc2[0], bi2[0]);

    // branch 1: param
    run_branch(1, s_st[1], fpn, pp, buf1[1], buf2[1], wt1[1], wt2[1],
               sc1[1], bi1[1], sc2[1], bi2[1]);
    head_conv<2><<<hgrid, 256, 0, s_st[1]>>>(buf2[1], w_p3, bias_p3,
                                             out + 2 * seg, 128, sc2[1], bi2[1]);

    // branch 2: shift
    run_branch(2, s_st[2], fpn, sh, buf1[2], buf2[2], wt1[2], wt2[2],
               sc1[2], bi1[2], sc2[2], bi2[2]);
    head_conv<8><<<hgrid, 256, 0, s_st[2]>>>(buf2[2], w_s3, bias_s3,
                                             out + 4 * seg, 128, sc2[2], bi2[2]);

    // join
    for (int i = 0; i < 3; i++) {
        cudaEventRecord(s_join[i], s_st[i]);
        cudaStreamWaitEvent(0, s_join[i], 0);
    }
}

// round 6
// speedup vs baseline: 4.3832x; 1.1342x over previous
#include <cuda_runtime.h>
#include <cstdint>
#include <cstddef>

#define H_   160
#define W_   160
#define B_   4
#define HW   (H_ * W_)
#define PIX  (B_ * HW)          // 102400
#define K2   2304               // 9 * 256
#define NCHK 72                 // K chunks of 32

// ---------------- scratch (device globals; no allocation allowed) ----------
__device__ float g_buf1[3][(size_t)B_ * 256 * HW];
__device__ float g_buf2[3][(size_t)B_ * 128 * HW];
__device__ float g_wt1[3][2 * 72 * 4096];         // packed conv1 weights
__device__ float g_wt2[3][1 * 72 * 4096];         // packed conv2 weights
__device__ float g_sc1[3][256], g_bi1[3][256];
__device__ float g_sc2[3][128], g_bi2[3][128];
__device__ float g_wcat[2 * 128 * 9];
__device__ float g_bcat[2];

__device__ __forceinline__ float to_tf32(float x) {
    float r; asm("cvt.rna.tf32.f32 %0, %1;" : "=f"(r) : "f"(x)); return r;
}
__device__ __forceinline__ uint32_t smem_u32(const void* p) {
    uint32_t a;
    asm("{ .reg .u64 t; cvta.to.shared.u64 t, %1; cvt.u32.u64 %0, t; }" : "=r"(a) : "l"(p));
    return a;
}
__device__ __forceinline__ void cp_async16(uint32_t saddr, const void* g) {
    asm volatile("cp.async.cg.shared.global [%0], [%1], 16;" :: "r"(saddr), "l"(g));
}
#define CP_COMMIT() asm volatile("cp.async.commit_group;" ::: "memory")
#define CP_WAIT0()  asm volatile("cp.async.wait_group 0;" ::: "memory")

// mma.sync m16n8k8 tf32 (baseline PTX, valid on plain sm_103 target)
__device__ __forceinline__ void mma8(float* d, const uint32_t* a, uint32_t b0, uint32_t b1) {
    asm volatile(
        "mma.sync.aligned.m16n8k8.row.col.f32.tf32.tf32.f32 "
        "{%0,%1,%2,%3}, {%4,%5,%6,%7}, {%8,%9}, {%0,%1,%2,%3};"
        : "+f"(d[0]), "+f"(d[1]), "+f"(d[2]), "+f"(d[3])
        : "r"(a[0]), "r"(a[1]), "r"(a[2]), "r"(a[3]), "r"(b0), "r"(b1));
}

// smem per stage: A packed 4096 floats + B 16 rows x 132 float2 (264 floats)
#define BROW_F2  132
#define B_FLTS   (16 * 2 * BROW_F2)          // 4224
#define STG_FLTS (4096 + B_FLTS)             // 8320
#define SMEM_DYN (2 * STG_FLTS * 4)          // 66560 B

// ---------------- weight pack: [oc][ci][tap] -> fragment-ordered tf32 ------
__global__ void wt_pack(const float* __restrict__ w, float* __restrict__ dst, int Cout)
{
    int i = blockIdx.x * 256 + threadIdx.x;
    if (i >= Cout * K2) return;
    int j     = i & 3;
    int lane  = (i >> 2) & 31;
    int mt    = (i >> 7) & 1;
    int og    = (i >> 8) & 3;
    int ks    = (i >> 10) & 3;
    int chunk = (i >> 12) % 72;
    int ocblk = i / (72 * 4096);
    int q = lane & 3, r = lane >> 2;
    int tap = chunk >> 3;
    int ci  = (chunk & 7) * 32 + ks * 8 + q + (j >> 1) * 4;
    int oc  = ocblk * 128 + og * 32 + r + mt * 16 + (j & 1) * 8;
    dst[i] = to_tf32(w[((size_t)oc * 256 + ci) * 9 + tap]);
}

// ---------------- concat two 1-channel head weights -------------------------
__global__ void concat_heads(const float* __restrict__ wa, const float* __restrict__ wb,
                             const float* __restrict__ ba, const float* __restrict__ bb,
                             float* __restrict__ w, float* __restrict__ bias)
{
    int i = blockIdx.x * 256 + threadIdx.x;
    if (i < 1152) w[i] = wa[i];
    else if (i < 2304) w[i] = wb[i - 1152];
    if (i == 0) { bias[0] = ba[0]; bias[1] = bb[0]; }
}

// ---------------- mma.sync tf32 implicit-GEMM 3x3 conv ----------------------
// grid: (PIX/128, Cout/128)  block: 256 threads (8 warps, warp = 32oc x 64px)
template <bool HAS_BN>
__global__ __launch_bounds__(256, 2)
void conv3x3_mma(const float* __restrict__ X, const float* __restrict__ wtp,
                 float* __restrict__ Y, int Cout,
                 const float* __restrict__ bnsc, const float* __restrict__ bnbi)
{
    extern __shared__ float sm[];
    const uint32_t smb = smem_u32(sm);

    const int tid  = threadIdx.x;
    const int wid  = tid >> 5;
    const int lane = tid & 31;
    const int r    = lane >> 2;
    const int q    = lane & 3;

    const int p0   = blockIdx.x * 128;
    const int oc0  = blockIdx.y * 128;
    const int bimg = p0 / HW;
    const int hw0  = p0 - bimg * HW;
    const float* Xb  = X + (size_t)bimg * 256 * HW;
    const float* wcb = wtp + (size_t)blockIdx.y * (72 * 4096);

    const int ocb = (wid & 3) * 32;
    const int pxb = (wid >> 2) * 64;

    // B staging ownership: thread -> (ks_o, qg) pair rows
    const int ks_o = wid >> 1;
    const int qg   = (wid & 1) * 2;
    int kj[4];
    #pragma unroll
    for (int j = 0; j < 4; j++) kj[j] = ks_o * 8 + qg + (j & 1) + 4 * (j >> 1);

    int pg[4], hh[4], ww[4];
    #pragma unroll
    for (int g = 0; g < 4; g++) {
        int p = hw0 + g * 32 + lane;
        pg[g] = p; hh[g] = p / W_; ww[g] = p % W_;
    }

    float acc[2][8][4];
    #pragma unroll
    for (int mt = 0; mt < 2; mt++)
        #pragma unroll
        for (int nt = 0; nt < 8; nt++)
            #pragma unroll
            for (int i = 0; i < 4; i++) acc[mt][nt][i] = 0.f;

    float rb[4][4];

    auto copyA = [&](int c, int s) {
        const float* gsrc = wcb + (size_t)c * 4096 + tid * 4;
        uint32_t sdst = smb + (s * STG_FLTS + tid * 4) * 4;
        #pragma unroll
        for (int i = 0; i < 4; i++)
            cp_async16(sdst + i * 4096, gsrc + i * 1024);
    };

    auto stageB = [&](int c) {
        const int tap = c >> 3;
        const int ci0 = (c & 7) << 5;
        const int dh  = tap / 3 - 1;
        const int dw  = tap % 3 - 1;
        float sc[4], bi[4];
        if (HAS_BN) {
            #pragma unroll
            for (int j = 0; j < 4; j++) {
                sc[j] = bnsc[ci0 + kj[j]];
                bi[j] = bnbi[ci0 + kj[j]];
            }
        }
        const float* base = Xb + (size_t)ci0 * HW + dh * W_ + dw;
        #pragma unroll
        for (int g = 0; g < 4; g++) {
            bool v = (unsigned)(hh[g] + dh) < (unsigned)H_ &&
                     (unsigned)(ww[g] + dw) < (unsigned)W_;
            const float* sp = base + pg[g];
            #pragma unroll
            for (int j = 0; j < 4; j++) {
                float x = v ? sp[(size_t)kj[j] * HW] : 0.f;
                if (HAS_BN) x = v ? fmaxf(fmaf(x, sc[j], bi[j]), 0.f) : 0.f;
                rb[g][j] = to_tf32(x);
            }
        }
    };

    auto stsB = [&](int s) {
        float2* sB2 = (float2*)(sm + s * STG_FLTS + 4096);
        #pragma unroll
        for (int g = 0; g < 4; g++)
            #pragma unroll
            for (int qi = 0; qi < 2; qi++)
                sB2[(ks_o * 4 + qg + qi) * BROW_F2 + g * 32 + lane] =
                    make_float2(rb[g][qi], rb[g][qi + 2]);
    };

    auto compute = [&](int s) {
        const float*  sA  = sm + s * STG_FLTS;
        const float2* sB2 = (const float2*)(sA + 4096);
        #pragma unroll
        for (int ks = 0; ks < 4; ks++) {
            const float* ap = sA + ks * 1024 + (wid & 3) * 256 + lane * 4;
            float4 qa0 = *(const float4*)ap;
            float4 qa1 = *(const float4*)(ap + 128);
            uint32_t a0[4] = { __float_as_uint(qa0.x), __float_as_uint(qa0.y),
                               __float_as_uint(qa0.z), __float_as_uint(qa0.w) };
            uint32_t a1[4] = { __float_as_uint(qa1.x), __float_as_uint(qa1.y),
                               __float_as_uint(qa1.z), __float_as_uint(qa1.w) };
            const float2* bP = sB2 + (ks * 4 + q) * BROW_F2 + pxb + r;
            #pragma unroll
            for (int nt = 0; nt < 8; nt++) {
                float2 bv = bP[nt * 8];
                uint32_t b0 = __float_as_uint(bv.x);
                uint32_t b1 = __float_as_uint(bv.y);
                mma8(acc[0][nt], a0, b0, b1);
                mma8(acc[1][nt], a1, b0, b1);
            }
        }
    };

    // prologue
    copyA(0, 0); CP_COMMIT();
    stageB(0); stsB(0);
    CP_WAIT0();
    __syncthreads();

    for (int c = 0; c < NCHK; c++) {
        const int cur = c & 1, nxt = cur ^ 1;
        if (c + 1 < NCHK) {
            copyA(c + 1, nxt); CP_COMMIT();
            stageB(c + 1);
        }
        compute(cur);
        if (c + 1 < NCHK) {
            stsB(nxt);
            CP_WAIT0();
            __syncthreads();
        }
    }

    #pragma unroll
    for (int mt = 0; mt < 2; mt++) {
        const int oc = oc0 + ocb + mt * 16 + r;
        float* Yr = Y + ((size_t)bimg * Cout + oc) * HW + hw0 + pxb + q * 2;
        #pragma unroll
        for (int nt = 0; nt < 8; nt++) {
            *(float2*)(Yr + nt * 8)                  = make_float2(acc[mt][nt][0], acc[mt][nt][1]);
            *(float2*)(Yr + nt * 8 + 8 * (size_t)HW) = make_float2(acc[mt][nt][2], acc[mt][nt][3]);
        }
    }
}

// ---------------- per-channel batch stats -> fused scale/bias ---------------
__global__ __launch_bounds__(1024)
void bn_stats(const float* __restrict__ X, int C,
              const float* __restrict__ gamma, const float* __restrict__ beta,
              float* __restrict__ osc, float* __restrict__ obi)
{
    const int c = blockIdx.x;
    float s = 0.f, s2 = 0.f;
    for (int b = 0; b < B_; b++) {
        const float* qp = X + ((size_t)b * C + c) * HW;
        for (int i = threadIdx.x; i < HW; i += 1024) {
            float v = qp[i];
            s += v; s2 += v * v;
        }
    }
    __shared__ float rs[1024], rs2[1024];
    rs[threadIdx.x] = s; rs2[threadIdx.x] = s2;
    __syncthreads();
    for (int o = 512; o > 0; o >>= 1) {
        if (threadIdx.x < o) {
            rs[threadIdx.x]  += rs[threadIdx.x + o];
            rs2[threadIdx.x] += rs2[threadIdx.x + o];
        }
        __syncthreads();
    }
    if (threadIdx.x == 0) {
        const float cnt = (float)(B_ * HW);
        float m   = rs[0] / cnt;
        float var = rs2[0] / cnt - m * m;
        float is  = rsqrtf(var + 1e-5f);
        float scl = gamma[c] * is;
        osc[c] = scl;
        obi[c] = beta[c] - m * scl;
    }
}

// ---------------- head conv: 3x3 + bias, BN+ReLU fused on input -------------
#define HTH 16
#define HTW 32

template <int CO>
__global__ __launch_bounds__(256)
void head_conv(const float* __restrict__ X, const float* __restrict__ Wt,
               const float* __restrict__ bias, float* __restrict__ Y, int Cin,
               const float* __restrict__ bnsc, const float* __restrict__ bnbi,
               size_t strideC, size_t strideB)
{
    const int tile = blockIdx.x;
    const int tw0  = (tile % (W_ / HTW)) * HTW;
    const int th0  = (tile / (W_ / HTW)) * HTH;
    const int b    = blockIdx.z;
    const int t    = threadIdx.x;
    const int col  = t & 31;
    const int rp   = (t >> 5) * 2;

    __shared__ float sX[8][HTH + 2][HTW + 4];
    __shared__ float sW[8][9][CO];

    float acc[2][CO];
    #pragma unroll
    for (int r = 0; r < 2; r++)
        #pragma unroll
        for (int o = 0; o < CO; o++) acc[r][o] = 0.f;

    const float* Xb = X + (size_t)b * Cin * HW;

    for (int ci0 = 0; ci0 < Cin; ci0 += 8) {
        __syncthreads();
        for (int e = t; e < 8 * (HTH + 2) * 34; e += 256) {
            int ci  = e / ((HTH + 2) * 34);
            int rem = e % ((HTH + 2) * 34);
            int r   = rem / 34;
            int c   = rem % 34;
            int gh  = th0 + r - 1;
            int gw  = tw0 + c - 1;
            float v = 0.f;
            if (gh >= 0 && gh < H_ && gw >= 0 && gw < W_) {
                float x = Xb[(size_t)(ci0 + ci) * HW + gh * W_ + gw];
                v = fmaxf(fmaf(x, bnsc[ci0 + ci], bnbi[ci0 + ci]), 0.f);
            }
            sX[ci][r][c] = v;
        }
        for (int e = t; e < 8 * 9 * CO; e += 256) {
            int ci  = e / (9 * CO);
            int rem = e % (9 * CO);
            int tap = rem / CO;
            int oc  = rem % CO;
            sW[ci][tap][oc] = Wt[((size_t)oc * Cin + ci0 + ci) * 9 + tap];
        }
        __syncthreads();

        #pragma unroll 1
        for (int ci = 0; ci < 8; ci++) {
            float xv[4][3];
            #pragma unroll
            for (int rr = 0; rr < 4; rr++)
                #pragma unroll
                for (int cc = 0; cc < 3; cc++)
                    xv[rr][cc] = sX[ci][rp + rr][col + cc];
            #pragma unroll
            for (int oc = 0; oc < CO; oc++) {
                float w[9];
                #pragma unroll
                for (int tp = 0; tp < 9; tp++) w[tp] = sW[ci][tp][oc];
                #pragma unroll
                for (int orow = 0; orow < 2; orow++) {
                    float s = acc[orow][oc];
                    #pragma unroll
                    for (int kh = 0; kh < 3; kh++)
                        #pragma unroll
                        for (int kw = 0; kw < 3; kw++)
                            s += w[kh * 3 + kw] * xv[orow + kh][kw];
                    acc[orow][oc] = s;
                }
            }
        }
    }

    #pragma unroll
    for (int oc = 0; oc < CO; oc++) {
        const float bz = bias[oc];
        #pragma unroll
        for (int orow = 0; orow < 2; orow++) {
            const int h = th0 + rp + orow;
            Y[oc * strideC + b * strideB + h * W_ + tw0 + col] = acc[orow][oc] + bz;
        }
    }
}

// ---------------- launcher ---------------------------------------------------
struct BranchPtrs {
    const float *w1, *g1, *b1, *w2, *g2, *b2;
};

static void run_branch(cudaStream_t st, const float* fpn, const BranchPtrs& P,
                       float* buf1, float* buf2, float* wt1, float* wt2,
                       float* sc1, float* bi1, float* sc2, float* bi2)
{
    wt_pack<<<(256 * K2 + 255) / 256, 256, 0, st>>>(P.w1, wt1, 256);
    wt_pack<<<(128 * K2 + 255) / 256, 256, 0, st>>>(P.w2, wt2, 128);
    conv3x3_mma<false><<<dim3(PIX / 128, 2), 256, SMEM_DYN, st>>>(
        fpn, wt1, buf1, 256, nullptr, nullptr);
    bn_stats<<<256, 1024, 0, st>>>(buf1, 256, P.g1, P.b1, sc1, bi1);
    conv3x3_mma<true><<<dim3(PIX / 128, 1), 256, SMEM_DYN, st>>>(
        buf1, wt2, buf2, 128, sc1, bi1);
    bn_stats<<<128, 1024, 0, st>>>(buf2, 128, P.g2, P.b2, sc2, bi2);
}

extern "C" void kernel_launch(void* const* d_in, const int* in_sizes, int n_in,
                              void* d_out, int out_size)
{
    const float* fpn        = (const float*)d_in[0];
    BranchPtrs sc = { (const float*)d_in[1],  (const float*)d_in[2],  (const float*)d_in[3],
                      (const float*)d_in[4],  (const float*)d_in[5],  (const float*)d_in[6] };
    const float* w_shrink   = (const float*)d_in[7];
    const float* bias_shrink= (const float*)d_in[8];
    const float* w_cent     = (const float*)d_in[9];
    const float* bias_cent  = (const float*)d_in[10];
    BranchPtrs pp = { (const float*)d_in[11], (const float*)d_in[12], (const float*)d_in[13],
                      (const float*)d_in[14], (const float*)d_in[15], (const float*)d_in[16] };
    const float* w_p3       = (const float*)d_in[17];
    const float* bias_p3    = (const float*)d_in[18];
    BranchPtrs sh = { (const float*)d_in[19], (const float*)d_in[20], (const float*)d_in[21],
                      (const float*)d_in[22], (const float*)d_in[23], (const float*)d_in[24] };
    const float* w_s3       = (const float*)d_in[25];
    const float* bias_s3    = (const float*)d_in[26];

    float* out = (float*)d_out;

    static cudaStream_t s_st[3];
    static cudaEvent_t  s_fork, s_join[3];
    static int s_init = 0;
    if (!s_init) {
        for (int i = 0; i < 3; i++) {
            cudaStreamCreateWithFlags(&s_st[i], cudaStreamNonBlocking);
            cudaEventCreateWithFlags(&s_join[i], cudaEventDisableTiming);
        }
        cudaEventCreateWithFlags(&s_fork, cudaEventDisableTiming);
        s_init = 1;
    }

    float *buf1[3], *buf2[3], *wt1[3], *wt2[3];
    float *sc1[3], *bi1[3], *sc2[3], *bi2[3];
    float *wcat, *bcat;
    {
        float *p;
        cudaGetSymbolAddress((void**)&p, g_buf1);
        for (int i = 0; i < 3; i++) buf1[i] = p + (size_t)i * B_ * 256 * HW;
        cudaGetSymbolAddress((void**)&p, g_buf2);
        for (int i = 0; i < 3; i++) buf2[i] = p + (size_t)i * B_ * 128 * HW;
        cudaGetSymbolAddress((void**)&p, g_wt1);
        for (int i = 0; i < 3; i++) wt1[i] = p + (size_t)i * 2 * 72 * 4096;
        cudaGetSymbolAddress((void**)&p, g_wt2);
        for (int i = 0; i < 3; i++) wt2[i] = p + (size_t)i * 72 * 4096;
        cudaGetSymbolAddress((void**)&p, g_sc1);
        for (int i = 0; i < 3; i++) sc1[i] = p + i * 256;
        cudaGetSymbolAddress((void**)&p, g_bi1);
        for (int i = 0; i < 3; i++) bi1[i] = p + i * 256;
        cudaGetSymbolAddress((void**)&p, g_sc2);
        for (int i = 0; i < 3; i++) sc2[i] = p + i * 128;
        cudaGetSymbolAddress((void**)&p, g_bi2);
        for (int i = 0; i < 3; i++) bi2[i] = p + i * 128;
        cudaGetSymbolAddress((void**)&wcat, g_wcat);
        cudaGetSymbolAddress((void**)&bcat, g_bcat);
    }

    cudaFuncSetAttribute(conv3x3_mma<false>, cudaFuncAttributeMaxDynamicSharedMemorySize, SMEM_DYN);
    cudaFuncSetAttribute(conv3x3_mma<true>,  cudaFuncAttributeMaxDynamicSharedMemorySize, SMEM_DYN);

    dim3 hgrid(50, 1, B_);
    const size_t seg = (size_t)B_ * HW;

    // fork
    cudaEventRecord(s_fork, 0);
    for (int i = 0; i < 3; i++) cudaStreamWaitEvent(s_st[i], s_fork, 0);

    // branch 0: sc -> shrink + centroid (fused CO=2 head via weight concat)
    concat_heads<<<9, 256, 0, s_st[0]>>>(w_shrink, w_cent, bias_shrink, bias_cent,
                                         wcat, bcat);
    run_branch(s_st[0], fpn, sc, buf1[0], buf2[0], wt1[0], wt2[0],
               sc1[0], bi1[0], sc2[0], bi2[0]);
    head_conv<2><<<hgrid, 256, 0, s_st[0]>>>(buf2[0], wcat, bcat, out, 128,
                                             sc2[0], bi2[0], seg, (size_t)HW);

    // branch 1: param (B,2,H,W)
    run_branch(s_st[1], fpn, pp, buf1[1], buf2[1], wt1[1], wt2[1],
               sc1[1], bi1[1], sc2[1], bi2[1]);
    head_conv<2><<<hgrid, 256, 0, s_st[1]>>>(buf2[1], w_p3, bias_p3, out + 2 * seg, 128,
                                             sc2[1], bi2[1], (size_t)HW, (size_t)(2 * HW));

    // branch 2: shift (B,8,H,W)
    run_branch(s_st[2], fpn, sh, buf1[2], buf2[2], wt1[2], wt2[2],
               sc1[2], bi1[2], sc2[2], bi2[2]);
    head_conv<8><<<hgrid, 256, 0, s_st[2]>>>(buf2[2], w_s3, bias_s3, out + 4 * seg, 128,
                                             sc2[2], bi2[2], (size_t)HW, (size_t)(8 * HW));

    // join
    for (int i = 0; i < 3; i++) {
        cudaEventRecord(s_join[i], s_st[i]);
        cudaStreamWaitEvent(0, s_join[i], 0);
    }
}

// round 7
// speedup vs baseline: 7.0363x; 1.6053x over previous
#include <cuda_runtime.h>
#include <cuda_fp16.h>
#include <cstdint>
#include <cstddef>

#define H_   160
#define W_   160
#define B_   4
#define HW   (H_ * W_)
#define PIX  (B_ * HW)          // 102400
#define K2   2304               // 9 * 256
#define NCHK 72                 // K chunks of 32

// ---------------- scratch (device globals; no allocation allowed) ----------
__device__ float  g_buf1[3][(size_t)B_ * 256 * HW];
__device__ float  g_buf2[3][(size_t)B_ * 128 * HW];
__device__ __half g_wt1[3][2 * 72 * 4096];        // packed fp16 conv1 weights
__device__ __half g_wt2[3][1 * 72 * 4096];        // packed fp16 conv2 weights
__device__ float  g_sc1[3][256], g_bi1[3][256];
__device__ float  g_sc2[3][128], g_bi2[3][128];
__device__ float  g_wcat[2 * 128 * 9];
__device__ float  g_bcat[2];

__device__ __forceinline__ uint32_t smem_u32(const void* p) {
    uint32_t a;
    asm("{ .reg .u64 t; cvta.to.shared.u64 t, %1; cvt.u32.u64 %0, t; }" : "=r"(a) : "l"(p));
    return a;
}
__device__ __forceinline__ void cp_async16(uint32_t saddr, const void* g) {
    asm volatile("cp.async.cg.shared.global [%0], [%1], 16;" :: "r"(saddr), "l"(g));
}
#define CP_COMMIT() asm volatile("cp.async.commit_group;" ::: "memory")
#define CP_WAIT0()  asm volatile("cp.async.wait_group 0;" ::: "memory")

__device__ __forceinline__ uint32_t pack2h(float x, float y) {
    __half2 h = __floats2half2_rn(x, y);
    return *(uint32_t*)&h;     // low = x, high = y
}

// mma.sync m16n8k16 fp16 with fp32 accum (baseline PTX sm_80+)
__device__ __forceinline__ void mma16(float* d, const uint32_t* a, uint32_t b0, uint32_t b1) {
    asm volatile(
        "mma.sync.aligned.m16n8k16.row.col.f32.f16.f16.f32 "
        "{%0,%1,%2,%3}, {%4,%5,%6,%7}, {%8,%9}, {%0,%1,%2,%3};"
        : "+f"(d[0]), "+f"(d[1]), "+f"(d[2]), "+f"(d[3])
        : "r"(a[0]), "r"(a[1]), "r"(a[2]), "r"(a[3]), "r"(b0), "r"(b1));
}

// smem per stage: A fragment-packed 8192 B + B 8 rows x 132 uint2 (8448 B)
#define BROW_U2   132
#define A_BYTES   8192
#define B_BYTES   (8 * BROW_U2 * 8)      // 8448
#define STG_BYTES (A_BYTES + B_BYTES)    // 16640
#define SMEM_DYN  (2 * STG_BYTES)        // 33280

// ---------------- weight pack: [oc][ci][tap] -> m16n8k16 fragment order ----
__global__ void wt_pack(const float* __restrict__ w, __half* __restrict__ dst, int Cout)
{
    int i = blockIdx.x * 256 + threadIdx.x;
    if (i >= Cout * K2) return;
    int h     = i & 1;
    int jreg  = (i >> 1) & 3;
    int lane  = (i >> 3) & 31;
    int sub   = (i >> 8) & 15;      // ks*8 + og*2 + mt
    int chunk = (i >> 12) % 72;
    int ocblk = i / (72 * 4096);
    int ks = sub >> 3, og = (sub >> 1) & 3, mt = sub & 1;
    int q = lane & 3, r = lane >> 2;
    int row16 = r + 8 * (jreg & 1);
    int kk    = 2 * q + h + 8 * (jreg >> 1);
    int oc  = ocblk * 128 + og * 32 + mt * 16 + row16;
    int ci  = (chunk & 7) * 32 + ks * 16 + kk;
    int tap = chunk >> 3;
    dst[i] = __float2half_rn(w[((size_t)oc * 256 + ci) * 9 + tap]);
}

// ---------------- concat two 1-channel head weights -------------------------
__global__ void concat_heads(const float* __restrict__ wa, const float* __restrict__ wb,
                             const float* __restrict__ ba, const float* __restrict__ bb,
                             float* __restrict__ w, float* __restrict__ bias)
{
    int i = blockIdx.x * 256 + threadIdx.x;
    if (i < 1152) w[i] = wa[i];
    else if (i < 2304) w[i] = wb[i - 1152];
    if (i == 0) { bias[0] = ba[0]; bias[1] = bb[0]; }
}

// ---------------- fp16 mma.sync implicit-GEMM 3x3 conv ----------------------
// grid: (PIX/128, Cout/128)  block: 256 threads (8 warps, warp = 32oc x 64px)
template <bool HAS_BN>
__global__ __launch_bounds__(256, 2)
void conv3x3_mma(const float* __restrict__ X, const __half* __restrict__ wtp,
                 float* __restrict__ Y, int Cout,
                 const float* __restrict__ bnsc, const float* __restrict__ bnbi)
{
    extern __shared__ char sm[];
    const uint32_t smb = smem_u32(sm);

    const int tid  = threadIdx.x;
    const int wid  = tid >> 5;
    const int lane = tid & 31;
    const int r    = lane >> 2;
    const int q    = lane & 3;

    const int p0   = blockIdx.x * 128;
    const int oc0  = blockIdx.y * 128;
    const int bimg = p0 / HW;
    const int hw0  = p0 - bimg * HW;
    const float*  Xb  = X + (size_t)bimg * 256 * HW;
    const __half* wcb = wtp + (size_t)blockIdx.y * (72 * 4096);

    const int ocb = (wid & 3) * 32;
    const int pxb = (wid >> 2) * 64;

    // B staging: warp wid owns B row wid; k base within chunk:
    const int k0 = (wid >> 2) * 16 + (wid & 3) * 2;   // halves k0,k0+1,k0+8,k0+9

    int pg[4], hh[4], ww[4];
    #pragma unroll
    for (int g = 0; g < 4; g++) {
        int p = hw0 + g * 32 + lane;
        pg[g] = p; hh[g] = p / W_; ww[g] = p % W_;
    }

    float acc[2][8][4];
    #pragma unroll
    for (int mt = 0; mt < 2; mt++)
        #pragma unroll
        for (int nt = 0; nt < 8; nt++)
            #pragma unroll
            for (int i = 0; i < 4; i++) acc[mt][nt][i] = 0.f;

    uint2 rb[4];

    auto copyA = [&](int c, int s) {
        const char* g = (const char*)wcb + (size_t)c * 8192 + tid * 16;
        uint32_t d = smb + s * STG_BYTES + tid * 16;
        cp_async16(d, g);
        cp_async16(d + 4096, g + 4096);
    };

    auto stageB = [&](int c) {
        const int tap = c >> 3;
        const int ci0 = (c & 7) << 5;
        const int dh  = tap / 3 - 1;
        const int dw  = tap % 3 - 1;
        float sc0 = 0.f, sc1 = 0.f, sc2 = 0.f, sc3 = 0.f;
        float bi0 = 0.f, bi1 = 0.f, bi2 = 0.f, bi3 = 0.f;
        if (HAS_BN) {
            sc0 = bnsc[ci0 + k0];     bi0 = bnbi[ci0 + k0];
            sc1 = bnsc[ci0 + k0 + 1]; bi1 = bnbi[ci0 + k0 + 1];
            sc2 = bnsc[ci0 + k0 + 8]; bi2 = bnbi[ci0 + k0 + 8];
            sc3 = bnsc[ci0 + k0 + 9]; bi3 = bnbi[ci0 + k0 + 9];
        }
        const float* base = Xb + (size_t)(ci0 + k0) * HW + dh * W_ + dw;
        #pragma unroll
        for (int g = 0; g < 4; g++) {
            bool v = (unsigned)(hh[g] + dh) < (unsigned)H_ &&
                     (unsigned)(ww[g] + dw) < (unsigned)W_;
            const float* sp = base + pg[g];
            float x0 = v ? sp[0]              : 0.f;
            float x1 = v ? sp[(size_t)HW]     : 0.f;
            float x2 = v ? sp[(size_t)8 * HW] : 0.f;
            float x3 = v ? sp[(size_t)9 * HW] : 0.f;
            if (HAS_BN) {
                x0 = v ? fmaxf(fmaf(x0, sc0, bi0), 0.f) : 0.f;
                x1 = v ? fmaxf(fmaf(x1, sc1, bi1), 0.f) : 0.f;
                x2 = v ? fmaxf(fmaf(x2, sc2, bi2), 0.f) : 0.f;
                x3 = v ? fmaxf(fmaf(x3, sc3, bi3), 0.f) : 0.f;
            }
            rb[g] = make_uint2(pack2h(x0, x1), pack2h(x2, x3));
        }
    };

    auto stsB = [&](int s) {
        uint2* sB2 = (uint2*)(sm + s * STG_BYTES + A_BYTES);
        #pragma unroll
        for (int g = 0; g < 4; g++)
            sB2[wid * BROW_U2 + g * 32 + lane] = rb[g];
    };

    auto compute = [&](int s) {
        const char*  sbase = sm + s * STG_BYTES;
        const uint2* sB2   = (const uint2*)(sbase + A_BYTES);
        #pragma unroll
        for (int ks = 0; ks < 2; ks++) {
            const uint4* aPtr = (const uint4*)(sbase + ((ks * 4 + (wid & 3)) * 2) * 512) + lane;
            uint4 A0 = aPtr[0];        // mt=0 fragment (16B)
            uint4 A1 = aPtr[32];       // mt=1 fragment (+512B)
            uint32_t a0[4] = { A0.x, A0.y, A0.z, A0.w };
            uint32_t a1[4] = { A1.x, A1.y, A1.z, A1.w };
            const uint2* bP = sB2 + (ks * 4 + q) * BROW_U2 + pxb + r;
            #pragma unroll
            for (int nt = 0; nt < 8; nt++) {
                uint2 b = bP[nt * 8];
                mma16(acc[0][nt], a0, b.x, b.y);
                mma16(acc[1][nt], a1, b.x, b.y);
            }
        }
    };

    // prologue
    copyA(0, 0); CP_COMMIT();
    stageB(0); stsB(0);
    CP_WAIT0();
    __syncthreads();

    for (int c = 0; c < NCHK; c++) {
        const int cur = c & 1, nxt = cur ^ 1;
        if (c + 1 < NCHK) {
            copyA(c + 1, nxt); CP_COMMIT();
            stageB(c + 1);
        }
        compute(cur);
        if (c + 1 < NCHK) {
            stsB(nxt);
            CP_WAIT0();
            __syncthreads();
        }
    }

    #pragma unroll
    for (int mt = 0; mt < 2; mt++) {
        const int oc = oc0 + ocb + mt * 16 + r;
        float* Yr = Y + ((size_t)bimg * Cout + oc) * HW + hw0 + pxb + q * 2;
        #pragma unroll
        for (int nt = 0; nt < 8; nt++) {
            *(float2*)(Yr + nt * 8)                  = make_float2(acc[mt][nt][0], acc[mt][nt][1]);
            *(float2*)(Yr + nt * 8 + 8 * (size_t)HW) = make_float2(acc[mt][nt][2], acc[mt][nt][3]);
        }
    }
}

// ---------------- per-channel batch stats -> fused scale/bias ---------------
__global__ __launch_bounds__(1024)
void bn_stats(const float* __restrict__ X, int C,
              const float* __restrict__ gamma, const float* __restrict__ beta,
              float* __restrict__ osc, float* __restrict__ obi)
{
    const int c = blockIdx.x;
    float s = 0.f, s2 = 0.f;
    for (int b = 0; b < B_; b++) {
        const float* qp = X + ((size_t)b * C + c) * HW;
        for (int i = threadIdx.x; i < HW; i += 1024) {
            float v = qp[i];
            s += v; s2 += v * v;
        }
    }
    __shared__ float rs[1024], rs2[1024];
    rs[threadIdx.x] = s; rs2[threadIdx.x] = s2;
    __syncthreads();
    for (int o = 512; o > 0; o >>= 1) {
        if (threadIdx.x < o) {
            rs[threadIdx.x]  += rs[threadIdx.x + o];
            rs2[threadIdx.x] += rs2[threadIdx.x + o];
        }
        __syncthreads();
    }
    if (threadIdx.x == 0) {
        const float cnt = (float)(B_ * HW);
        float m   = rs[0] / cnt;
        float var = rs2[0] / cnt - m * m;
        float is  = rsqrtf(var + 1e-5f);
        float scl = gamma[c] * is;
        osc[c] = scl;
        obi[c] = beta[c] - m * scl;
    }
}

// ---------------- head conv: 3x3 + bias, BN+ReLU fused on input -------------
#define HTH 16
#define HTW 32

template <int CO>
__global__ __launch_bounds__(256)
void head_conv(const float* __restrict__ X, const float* __restrict__ Wt,
               const float* __restrict__ bias, float* __restrict__ Y, int Cin,
               const float* __restrict__ bnsc, const float* __restrict__ bnbi,
               size_t strideC, size_t strideB)
{
    const int tile = blockIdx.x;
    const int tw0  = (tile % (W_ / HTW)) * HTW;
    const int th0  = (tile / (W_ / HTW)) * HTH;
    const int b    = blockIdx.z;
    const int t    = threadIdx.x;
    const int col  = t & 31;
    const int rp   = (t >> 5) * 2;

    __shared__ float sX[8][HTH + 2][HTW + 4];
    __shared__ float sW[8][9][CO];

    float acc[2][CO];
    #pragma unroll
    for (int r = 0; r < 2; r++)
        #pragma unroll
        for (int o = 0; o < CO; o++) acc[r][o] = 0.f;

    const float* Xb = X + (size_t)b * Cin * HW;

    for (int ci0 = 0; ci0 < Cin; ci0 += 8) {
        __syncthreads();
        for (int e = t; e < 8 * (HTH + 2) * 34; e += 256) {
            int ci  = e / ((HTH + 2) * 34);
            int rem = e % ((HTH + 2) * 34);
            int r   = rem / 34;
            int c   = rem % 34;
            int gh  = th0 + r - 1;
            int gw  = tw0 + c - 1;
            float v = 0.f;
            if (gh >= 0 && gh < H_ && gw >= 0 && gw < W_) {
                float x = Xb[(size_t)(ci0 + ci) * HW + gh * W_ + gw];
                v = fmaxf(fmaf(x, bnsc[ci0 + ci], bnbi[ci0 + ci]), 0.f);
            }
            sX[ci][r][c] = v;
        }
        for (int e = t; e < 8 * 9 * CO; e += 256) {
            int ci  = e / (9 * CO);
            int rem = e % (9 * CO);
            int tap = rem / CO;
            int oc  = rem % CO;
            sW[ci][tap][oc] = Wt[((size_t)oc * Cin + ci0 + ci) * 9 + tap];
        }
        __syncthreads();

        #pragma unroll 1
        for (int ci = 0; ci < 8; ci++) {
            float xv[4][3];
            #pragma unroll
            for (int rr = 0; rr < 4; rr++)
                #pragma unroll
                for (int cc = 0; cc < 3; cc++)
                    xv[rr][cc] = sX[ci][rp + rr][col + cc];
            #pragma unroll
            for (int oc = 0; oc < CO; oc++) {
                float w[9];
                #pragma unroll
                for (int tp = 0; tp < 9; tp++) w[tp] = sW[ci][tp][oc];
                #pragma unroll
                for (int orow = 0; orow < 2; orow++) {
                    float s = acc[orow][oc];
                    #pragma unroll
                    for (int kh = 0; kh < 3; kh++)
                        #pragma unroll
                        for (int kw = 0; kw < 3; kw++)
                            s += w[kh * 3 + kw] * xv[orow + kh][kw];
                    acc[orow][oc] = s;
                }
            }
        }
    }

    #pragma unroll
    for (int oc = 0; oc < CO; oc++) {
        const float bz = bias[oc];
        #pragma unroll
        for (int orow = 0; orow < 2; orow++) {
            const int h = th0 + rp + orow;
            Y[oc * strideC + b * strideB + h * W_ + tw0 + col] = acc[orow][oc] + bz;
        }
    }
}

// ---------------- launcher ---------------------------------------------------
struct BranchPtrs {
    const float *w1, *g1, *b1, *w2, *g2, *b2;
};

static void run_branch(cudaStream_t st, const float* fpn, const BranchPtrs& P,
                       float* buf1, float* buf2, __half* wt1, __half* wt2,
                       float* sc1, float* bi1, float* sc2, float* bi2)
{
    wt_pack<<<(256 * K2 + 255) / 256, 256, 0, st>>>(P.w1, wt1, 256);
    wt_pack<<<(128 * K2 + 255) / 256, 256, 0, st>>>(P.w2, wt2, 128);
    conv3x3_mma<false><<<dim3(PIX / 128, 2), 256, SMEM_DYN, st>>>(
        fpn, wt1, buf1, 256, nullptr, nullptr);
    bn_stats<<<256, 1024, 0, st>>>(buf1, 256, P.g1, P.b1, sc1, bi1);
    conv3x3_mma<true><<<dim3(PIX / 128, 1), 256, SMEM_DYN, st>>>(
        buf1, wt2, buf2, 128, sc1, bi1);
    bn_stats<<<128, 1024, 0, st>>>(buf2, 128, P.g2, P.b2, sc2, bi2);
}

extern "C" void kernel_launch(void* const* d_in, const int* in_sizes, int n_in,
                              void* d_out, int out_size)
{
    const float* fpn        = (const float*)d_in[0];
    BranchPtrs sc = { (const float*)d_in[1],  (const float*)d_in[2],  (const float*)d_in[3],
                      (const float*)d_in[4],  (const float*)d_in[5],  (const float*)d_in[6] };
    const float* w_shrink   = (const float*)d_in[7];
    const float* bias_shrink= (const float*)d_in[8];
    const float* w_cent     = (const float*)d_in[9];
    const float* bias_cent  = (const float*)d_in[10];
    BranchPtrs pp = { (const float*)d_in[11], (const float*)d_in[12], (const float*)d_in[13],
                      (const float*)d_in[14], (const float*)d_in[15], (const float*)d_in[16] };
    const float* w_p3       = (const float*)d_in[17];
    const float* bias_p3    = (const float*)d_in[18];
    BranchPtrs sh = { (const float*)d_in[19], (const float*)d_in[20], (const float*)d_in[21],
                      (const float*)d_in[22], (const float*)d_in[23], (const float*)d_in[24] };
    const float* w_s3       = (const float*)d_in[25];
    const float* bias_s3    = (const float*)d_in[26];

    float* out = (float*)d_out;

    static cudaStream_t s_st[3];
    static cudaEvent_t  s_fork, s_join[3];
    static int s_init = 0;
    if (!s_init) {
        for (int i = 0; i < 3; i++) {
            cudaStreamCreateWithFlags(&s_st[i], cudaStreamNonBlocking);
            cudaEventCreateWithFlags(&s_join[i], cudaEventDisableTiming);
        }
        cudaEventCreateWithFlags(&s_fork, cudaEventDisableTiming);
        s_init = 1;
    }

    float *buf1[3], *buf2[3];
    __half *wt1[3], *wt2[3];
    float *sc1[3], *bi1[3], *sc2[3], *bi2[3];
    float *wcat, *bcat;
    {
        float *p; __half *hp;
        cudaGetSymbolAddress((void**)&p, g_buf1);
        for (int i = 0; i < 3; i++) buf1[i] = p + (size_t)i * B_ * 256 * HW;
        cudaGetSymbolAddress((void**)&p, g_buf2);
        for (int i = 0; i < 3; i++) buf2[i] = p + (size_t)i * B_ * 128 * HW;
        cudaGetSymbolAddress((void**)&hp, g_wt1);
        for (int i = 0; i < 3; i++) wt1[i] = hp + (size_t)i * 2 * 72 * 4096;
        cudaGetSymbolAddress((void**)&hp, g_wt2);
        for (int i = 0; i < 3; i++) wt2[i] = hp + (size_t)i * 72 * 4096;
        cudaGetSymbolAddress((void**)&p, g_sc1);
        for (int i = 0; i < 3; i++) sc1[i] = p + i * 256;
        cudaGetSymbolAddress((void**)&p, g_bi1);
        for (int i = 0; i < 3; i++) bi1[i] = p + i * 256;
        cudaGetSymbolAddress((void**)&p, g_sc2);
        for (int i = 0; i < 3; i++) sc2[i] = p + i * 128;
        cudaGetSymbolAddress((void**)&p, g_bi2);
        for (int i = 0; i < 3; i++) bi2[i] = p + i * 128;
        cudaGetSymbolAddress((void**)&wcat, g_wcat);
        cudaGetSymbolAddress((void**)&bcat, g_bcat);
    }

    cudaFuncSetAttribute(conv3x3_mma<false>, cudaFuncAttributeMaxDynamicSharedMemorySize, SMEM_DYN);
    cudaFuncSetAttribute(conv3x3_mma<true>,  cudaFuncAttributeMaxDynamicSharedMemorySize, SMEM_DYN);

    dim3 hgrid(50, 1, B_);
    const size_t seg = (size_t)B_ * HW;

    // fork
    cudaEventRecord(s_fork, 0);
    for (int i = 0; i < 3; i++) cudaStreamWaitEvent(s_st[i], s_fork, 0);

    // branch 0: sc -> shrink + centroid (fused CO=2 head via weight concat)
    concat_heads<<<9, 256, 0, s_st[0]>>>(w_shrink, w_cent, bias_shrink, bias_cent,
                                         wcat, bcat);
    run_branch(s_st[0], fpn, sc, buf1[0], buf2[0], wt1[0], wt2[0],
               sc1[0], bi1[0], sc2[0], bi2[0]);
    head_conv<2><<<hgrid, 256, 0, s_st[0]>>>(buf2[0], wcat, bcat, out, 128,
                                             sc2[0], bi2[0], seg, (size_t)HW);

    // branch 1: param (B,2,H,W)
    run_branch(s_st[1], fpn, pp, buf1[1], buf2[1], wt1[1], wt2[1],
               sc1[1], bi1[1], sc2[1], bi2[1]);
    head_conv<2><<<hgrid, 256, 0, s_st[1]>>>(buf2[1], w_p3, bias_p3, out + 2 * seg, 128,
                                             sc2[1], bi2[1], (size_t)HW, (size_t)(2 * HW));

    // branch 2: shift (B,8,H,W)
    run_branch(s_st[2], fpn, sh, buf1[2], buf2[2], wt1[2], wt2[2],
               sc1[2], bi1[2], sc2[2], bi2[2]);
    head_conv<8><<<hgrid, 256, 0, s_st[2]>>>(buf2[2], w_s3, bias_s3, out + 4 * seg, 128,
                                             sc2[2], bi2[2], (size_t)HW, (size_t)(8 * HW));

    // join
    for (int i = 0; i < 3; i++) {
        cudaEventRecord(s_join[i], s_st[i]);
        cudaStreamWaitEvent(0, s_join[i], 0);
    }
}